// round 7
// baseline (speedup 1.0000x reference)
#include <cuda_runtime.h>
#include <cuda_bf16.h>
#include <cstdint>

typedef uint32_t u32;

#define SEQ 8192
#define DM  1024
#define DH  128

#define NEGINF __int_as_float(0xff800000u)

// ---------------- device scratch (no allocs allowed) ----------------
__device__ __align__(16) __nv_bfloat16 g_Xh[SEQ*DM],  g_Xl[SEQ*DM];
__device__ __align__(16) __nv_bfloat16 g_Wh[3*DH*DM], g_Wl[3*DH*DM];
__device__ __align__(16) __nv_bfloat16 g_Qh[SEQ*DH],  g_Ql[SEQ*DH];
__device__ __align__(16) __nv_bfloat16 g_Kh[SEQ*DH],  g_Kl[SEQ*DH];
__device__ __align__(16) __nv_bfloat16 g_Vth[DH*SEQ], g_Vtl[DH*SEQ];  // V transposed [dim][seq]
__device__ float g_Op[4*SEQ*DH];
__device__ float g_mrow[4*SEQ], g_lrow[4*SEQ];

// ---------------- helpers ----------------
__device__ __forceinline__ u32 s2u(const void* p){
    u32 a; asm("{ .reg .u64 t; cvta.to.shared.u64 t, %1; cvt.u32.u64 %0, t; }" : "=r"(a) : "l"(p)); return a;
}
__device__ __forceinline__ u32 pack_bf2(float lo, float hi){
    u32 r; asm("cvt.rn.satfinite.bf16x2.f32 %0, %1, %2;" : "=r"(r) : "f"(hi), "f"(lo)); return r;
}
__device__ __forceinline__ float bflo(u32 v){ return __uint_as_float(v << 16); }
__device__ __forceinline__ float bfhi(u32 v){ return __uint_as_float(v & 0xffff0000u); }
__device__ __forceinline__ void split2(float a, float b, u32 &h, u32 &l){
    h = pack_bf2(a, b);
    l = pack_bf2(a - bflo(h), b - bfhi(h));
}
__device__ __forceinline__ void ldsm4(u32 a, u32 &r0, u32 &r1, u32 &r2, u32 &r3){
    asm volatile("ldmatrix.sync.aligned.m8n8.x4.shared.b16 {%0,%1,%2,%3}, [%4];"
        : "=r"(r0), "=r"(r1), "=r"(r2), "=r"(r3) : "r"(a));
}
__device__ __forceinline__ void mma16816(float* d, u32 a0, u32 a1, u32 a2, u32 a3, u32 b0, u32 b1){
    asm volatile("mma.sync.aligned.m16n8k16.row.col.f32.bf16.bf16.f32 "
        "{%0,%1,%2,%3},{%4,%5,%6,%7},{%8,%9},{%0,%1,%2,%3};"
        : "+f"(d[0]), "+f"(d[1]), "+f"(d[2]), "+f"(d[3])
        : "r"(a0), "r"(a1), "r"(a2), "r"(a3), "r"(b0), "r"(b1));
}
__device__ __forceinline__ void cpa16(u32 dst, const void* src){
    asm volatile("cp.async.cg.shared.global [%0], [%1], 16;" :: "r"(dst), "l"(src));
}
#define CPCOMMIT() asm volatile("cp.async.commit_group;" ::: "memory")
#define CPWAIT0()  asm volatile("cp.async.wait_group 0;" ::: "memory")
#define CPWAIT1()  asm volatile("cp.async.wait_group 1;" ::: "memory")
#define GBAR(id)   asm volatile("bar.sync %0, 128;" :: "r"(id) : "memory")

// =====================================================================
// Kernel 0: fp32 -> split bf16 for X and the 3 W matrices (one launch)
// =====================================================================
__global__ void split_all_kernel(const float4* __restrict__ X,
                                 const float4* __restrict__ Wq,
                                 const float4* __restrict__ Wk,
                                 const float4* __restrict__ Wv)
{
    const int nX4 = SEQ*DM/4, nW4 = DH*DM/4;
    int i = blockIdx.x * blockDim.x + threadIdx.x;
    const float4* src; uint2 *dh, *dl; int off;
    if (i < nX4) {
        src = X; off = i;
        dh = (uint2*)g_Xh; dl = (uint2*)g_Xl;
    } else {
        int k = i - nX4;
        if (k >= 3*nW4) return;
        int mat = k / nW4; off = k - mat*nW4;
        src = (mat==0) ? Wq : (mat==1) ? Wk : Wv;
        dh = (uint2*)(g_Wh + (size_t)mat*DH*DM);
        dl = (uint2*)(g_Wl + (size_t)mat*DH*DM);
    }
    float4 v = src[off];
    u32 h0, l0, h1, l1;
    split2(v.x, v.y, h0, l0);
    split2(v.z, v.w, h1, l1);
    dh[off] = make_uint2(h0, h1);
    dl[off] = make_uint2(l0, l1);
}

// =====================================================================
// Kernel 1: QKV projection, split-bf16 3-term, cp.async 2-stage.
// grid(128, 3): M-tile 64. 256 thr = 8 warps (2m x 4n).
// =====================================================================
#define PSB   144
#define PXH   0
#define PXL   9216
#define PWH   18432
#define PWL   36864
#define PSSZ  55296

__global__ void __launch_bounds__(256,1) proj_kernel()
{
    extern __shared__ __align__(16) char sm[];
    const u32 sb = s2u(sm);

    const int tid = threadIdx.x, lane = tid & 31, wid = tid >> 5;
    const int wm = wid >> 2, wn = wid & 3;       // 2m x 4n
    const int m0 = blockIdx.x * 64, mat = blockIdx.y;
    const __nv_bfloat16* __restrict__ Wbh = g_Wh + (size_t)mat*DH*DM;
    const __nv_bfloat16* __restrict__ Wbl = g_Wl + (size_t)mat*DH*DM;
    const float scale = (mat==0) ? 0.08838834764831845f : 1.0f;

    const int aRow = lane & 15, aKB = (lane >> 4) << 3;
    const int bRow = (lane & 7) + ((lane >> 4) & 1) * 8, bKB = ((lane >> 3) & 1) << 3;

    auto issue = [&](int kc, int st){
        const u32 base = sb + st*PSSZ;
        #pragma unroll
        for (int it = 0; it < 2; ++it) {
            int idx = tid + it*256;
            int r = idx >> 3, c = idx & 7;
            cpa16(base + PXH + r*PSB + c*16, &g_Xh[(size_t)(m0 + r)*DM + kc*64 + c*8]);
            cpa16(base + PXL + r*PSB + c*16, &g_Xl[(size_t)(m0 + r)*DM + kc*64 + c*8]);
        }
        #pragma unroll
        for (int it = 0; it < 4; ++it) {
            int idx = tid + it*256;
            int r = idx >> 3, c = idx & 7;
            cpa16(base + PWH + r*PSB + c*16, &Wbh[(size_t)r*DM + kc*64 + c*8]);
            cpa16(base + PWL + r*PSB + c*16, &Wbl[(size_t)r*DM + kc*64 + c*8]);
        }
        CPCOMMIT();
    };

    float acc[2][4][4];
    #pragma unroll
    for (int i = 0; i < 2; ++i)
        #pragma unroll
        for (int j = 0; j < 4; ++j)
            #pragma unroll
            for (int c = 0; c < 4; ++c) acc[i][j][c] = 0.f;

    issue(0, 0);
    for (int kc = 0; kc < 16; ++kc) {
        const int st = kc & 1;
        const u32 base = sb + st*PSSZ;
        CPWAIT0();
        __syncthreads();
        if (kc + 1 < 16) issue(kc + 1, st ^ 1);

        #pragma unroll
        for (int ks = 0; ks < 4; ++ks) {
            u32 ah[2][4], al[2][4];
            #pragma unroll
            for (int mt = 0; mt < 2; ++mt) {
                u32 qa = base + PXH + (u32)((wm*32 + mt*16 + aRow)*PSB + (ks*16 + aKB)*2);
                ldsm4(qa,             ah[mt][0], ah[mt][1], ah[mt][2], ah[mt][3]);
                ldsm4(qa + (PXL-PXH), al[mt][0], al[mt][1], al[mt][2], al[mt][3]);
            }
            #pragma unroll
            for (int nb = 0; nb < 2; ++nb) {
                u32 bh[4], bl[4];
                u32 ba = base + PWH + (u32)((wn*32 + nb*16 + bRow)*PSB + (ks*16 + bKB)*2);
                ldsm4(ba,             bh[0], bh[1], bh[2], bh[3]);
                ldsm4(ba + (PWL-PWH), bl[0], bl[1], bl[2], bl[3]);
                #pragma unroll
                for (int mt = 0; mt < 2; ++mt) {
                    mma16816(acc[mt][nb*2],   ah[mt][0],ah[mt][1],ah[mt][2],ah[mt][3], bh[0], bh[1]);
                    mma16816(acc[mt][nb*2],   ah[mt][0],ah[mt][1],ah[mt][2],ah[mt][3], bl[0], bl[1]);
                    mma16816(acc[mt][nb*2],   al[mt][0],al[mt][1],al[mt][2],al[mt][3], bh[0], bh[1]);
                    mma16816(acc[mt][nb*2+1], ah[mt][0],ah[mt][1],ah[mt][2],ah[mt][3], bh[2], bh[3]);
                    mma16816(acc[mt][nb*2+1], ah[mt][0],ah[mt][1],ah[mt][2],ah[mt][3], bl[2], bl[3]);
                    mma16816(acc[mt][nb*2+1], al[mt][0],al[mt][1],al[mt][2],al[mt][3], bh[2], bh[3]);
                }
            }
        }
        __syncthreads();
    }

    #pragma unroll
    for (int mt = 0; mt < 2; ++mt) {
        const int r0 = m0 + wm*32 + mt*16 + (lane >> 2);
        const int r1 = r0 + 8;
        #pragma unroll
        for (int nt = 0; nt < 4; ++nt) {
            const int col = wn*32 + nt*8 + (lane & 3)*2;
            float c0 = acc[mt][nt][0]*scale, c1 = acc[mt][nt][1]*scale;
            float c2 = acc[mt][nt][2]*scale, c3 = acc[mt][nt][3]*scale;
            if (mat < 2) {
                __nv_bfloat16* GH = (mat==0) ? g_Qh : g_Kh;
                __nv_bfloat16* GL = (mat==0) ? g_Ql : g_Kl;
                u32 h, l;
                split2(c0, c1, h, l);
                *(u32*)&GH[(size_t)r0*DH + col] = h;  *(u32*)&GL[(size_t)r0*DH + col] = l;
                split2(c2, c3, h, l);
                *(u32*)&GH[(size_t)r1*DH + col] = h;  *(u32*)&GL[(size_t)r1*DH + col] = l;
            } else {
                float v[4] = {c0, c1, c2, c3};
                #pragma unroll
                for (int e = 0; e < 4; ++e) {
                    int d  = col + (e & 1);
                    int sq = (e < 2) ? r0 : r1;
                    __nv_bfloat16 h = __float2bfloat16_rn(v[e]);
                    g_Vth[(size_t)d*SEQ + sq] = h;
                    g_Vtl[(size_t)d*SEQ + sq] = __float2bfloat16_rn(v[e] - __bfloat162float(h));
                }
            }
        }
    }
}

// =====================================================================
// Kernel 2: causal flash attention, split-bf16 3-term.
// 128 CTAs x 256 thr = 2 INDEPENDENT groups of 4 warps. Each group:
// one 64-row q-tile (g0: pp, g1: 127-pp), two KV-quarters {qh, qh+2}.
// Group-local named barriers; overlap comes from cross-group warp
// scheduling on each SMSP (softmax of one group hides under the
// other group's HMMA stream).
// =====================================================================
#define ASB   272            // Q/K row stride bytes (128 kcols)
#define VSB   144            // V row stride bytes (64 key cols)
#define GQ    0              // Q hi (lo +17408)
#define GK    34816          // K hi (lo +17408)
#define GV    69632          // V hi (lo +18432)
#define GSZ   106496         // per-group smem

__global__ void __launch_bounds__(256,1) attn_kernel()
{
    extern __shared__ __align__(16) char sm[];
    const int tid = threadIdx.x, lane = tid & 31;
    const int g   = tid >> 7;          // group 0/1
    const int tg  = tid & 127;         // thread-in-group
    const int w4  = tg >> 5;           // warp-in-group 0..3
    const int barid = g + 1;

    const u32 gb = s2u(sm) + (u32)g*GSZ;
    const u32 qbh = gb + GQ, kbh = gb + GK, vbh = gb + GV;

    const int pp = blockIdx.x & 63;
    const int qh = blockIdx.x >> 6;    // 0/1
    const int T  = g ? (127 - pp) : pp;   // 64-row q-tile index

    const int aRow = lane & 15, aKB = (lane >> 4) << 3;
    const int bRow = (lane & 7) + ((lane >> 4) & 1) * 8, bKB = ((lane >> 3) & 1) << 3;
    const int rl0 = w4*16 + (lane >> 2);
    const int rl1 = rl0 + 8;

    auto issueK = [&](int j){
        #pragma unroll
        for (int it = 0; it < 8; ++it) {
            int idx = tg + it*128;
            int r = idx >> 4, c = idx & 15;
            cpa16(kbh         + r*ASB + c*16, &g_Kh[(size_t)(j*64 + r)*DH + c*8]);
            cpa16(kbh + 17408 + r*ASB + c*16, &g_Kl[(size_t)(j*64 + r)*DH + c*8]);
        }
        CPCOMMIT();
    };
    auto issueV = [&](int j){
        #pragma unroll
        for (int it = 0; it < 8; ++it) {
            int idx = tg + it*128;
            int r = idx >> 3, c = idx & 7;
            cpa16(vbh         + r*VSB + c*16, &g_Vth[(size_t)r*SEQ + j*64 + c*8]);
            cpa16(vbh + 18432 + r*VSB + c*16, &g_Vtl[(size_t)r*SEQ + j*64 + c*8]);
        }
        CPCOMMIT();
    };

    // ---- load Q once per group (reused by both quarter-units) ----
    #pragma unroll
    for (int it = 0; it < 8; ++it) {
        int idx = tg + it*128;
        int r = idx >> 4, c = idx & 15;
        cpa16(qbh         + r*ASB + c*16, &g_Qh[(size_t)(T*64 + r)*DH + c*8]);
        cpa16(qbh + 17408 + r*ASB + c*16, &g_Ql[(size_t)(T*64 + r)*DH + c*8]);
    }
    CPCOMMIT();

    const int Tt = T + 1;              // 64-key subtiles this tile attends
    const int Tq = (Tt + 3) >> 2;

    #pragma unroll 1
    for (int uq = 0; uq < 2; ++uq) {
        const int qq = qh + 2*uq;
        const int j0 = qq * Tq;
        const int j1 = (j0 + Tq < Tt) ? (j0 + Tq) : Tt;
        const int brow = qq*SEQ + T*64;

        if (j0 >= j1) {
            if (tg < 64) { g_mrow[brow + tg] = NEGINF; g_lrow[brow + tg] = 0.f; }
            continue;
        }

        issueK(j0);
        issueV(j0);
        CPWAIT1();          // Q (+K for uq=0) landed; V may fly
        GBAR(barid);

        float o[16][4];
        #pragma unroll
        for (int nt = 0; nt < 16; ++nt)
            #pragma unroll
            for (int c = 0; c < 4; ++c) o[nt][c] = 0.f;
        float m0r = NEGINF, m1r = NEGINF, l0 = 0.f, l1 = 0.f;

        float s[8][4];
        u32 ph2[16], pl2[16];

        #pragma unroll 1
        for (int j = j0; j < j1; ++j) {
            const bool hn = (j + 1 < j1);

            // ---- S = Q K^T (64 keys) ----
            #pragma unroll
            for (int nt = 0; nt < 8; ++nt)
                #pragma unroll
                for (int c = 0; c < 4; ++c) s[nt][c] = 0.f;
            #pragma unroll
            for (int ks = 0; ks < 8; ++ks) {
                u32 qhf[4], qlf[4];
                u32 qa = qbh + (u32)((w4*16 + aRow)*ASB + (ks*16 + aKB)*2);
                ldsm4(qa,         qhf[0], qhf[1], qhf[2], qhf[3]);
                ldsm4(qa + 17408, qlf[0], qlf[1], qlf[2], qlf[3]);
                #pragma unroll
                for (int nbp = 0; nbp < 4; ++nbp) {
                    u32 kh[4], kl[4];
                    u32 ba = kbh + (u32)((nbp*16 + bRow)*ASB + (ks*16 + bKB)*2);
                    ldsm4(ba,         kh[0], kh[1], kh[2], kh[3]);
                    ldsm4(ba + 17408, kl[0], kl[1], kl[2], kl[3]);
                    mma16816(s[nbp*2],   qhf[0],qhf[1],qhf[2],qhf[3], kh[0], kh[1]);
                    mma16816(s[nbp*2],   qhf[0],qhf[1],qhf[2],qhf[3], kl[0], kl[1]);
                    mma16816(s[nbp*2],   qlf[0],qlf[1],qlf[2],qlf[3], kh[0], kh[1]);
                    mma16816(s[nbp*2+1], qhf[0],qhf[1],qhf[2],qhf[3], kh[2], kh[3]);
                    mma16816(s[nbp*2+1], qhf[0],qhf[1],qhf[2],qhf[3], kl[2], kl[3]);
                    mma16816(s[nbp*2+1], qlf[0],qlf[1],qlf[2],qlf[3], kh[2], kh[3]);
                }
            }
            GBAR(barid);                 // group done reading K(j)
            if (hn) issueK(j + 1);       // refill K stage during softmax/PV

            // ---- causal mask (diagonal subtile) ----
            if (j == T) {
                const int gr0 = T*64 + rl0, gr1 = T*64 + rl1;
                #pragma unroll
                for (int nt = 0; nt < 8; ++nt) {
                    int gc = j*64 + nt*8 + (lane & 3)*2;
                    if (gc     > gr0) s[nt][0] = NEGINF;
                    if (gc + 1 > gr0) s[nt][1] = NEGINF;
                    if (gc     > gr1) s[nt][2] = NEGINF;
                    if (gc + 1 > gr1) s[nt][3] = NEGINF;
                }
            }

            // ---- online softmax (quad-local rows) ----
            float mx0 = NEGINF, mx1 = NEGINF;
            #pragma unroll
            for (int nt = 0; nt < 8; ++nt) {
                mx0 = fmaxf(mx0, fmaxf(s[nt][0], s[nt][1]));
                mx1 = fmaxf(mx1, fmaxf(s[nt][2], s[nt][3]));
            }
            mx0 = fmaxf(mx0, __shfl_xor_sync(0xffffffffu, mx0, 1));
            mx0 = fmaxf(mx0, __shfl_xor_sync(0xffffffffu, mx0, 2));
            mx1 = fmaxf(mx1, __shfl_xor_sync(0xffffffffu, mx1, 1));
            mx1 = fmaxf(mx1, __shfl_xor_sync(0xffffffffu, mx1, 2));

            float mn0 = fmaxf(m0r, mx0), mn1 = fmaxf(m1r, mx1);
            float mue0 = (mn0 == NEGINF) ? 0.f : mn0;
            float mue1 = (mn1 == NEGINF) ? 0.f : mn1;
            float al0 = __expf(m0r - mue0), al1 = __expf(m1r - mue1);

            float sum0 = 0.f, sum1 = 0.f;
            #pragma unroll
            for (int nt = 0; nt < 8; ++nt) {
                float p0 = __expf(s[nt][0] - mue0);
                float p1 = __expf(s[nt][1] - mue0);
                float p2 = __expf(s[nt][2] - mue1);
                float p3 = __expf(s[nt][3] - mue1);
                sum0 += p0 + p1;  sum1 += p2 + p3;
                split2(p0, p1, ph2[nt*2],   pl2[nt*2]);
                split2(p2, p3, ph2[nt*2+1], pl2[nt*2+1]);
            }
            sum0 += __shfl_xor_sync(0xffffffffu, sum0, 1);
            sum0 += __shfl_xor_sync(0xffffffffu, sum0, 2);
            sum1 += __shfl_xor_sync(0xffffffffu, sum1, 1);
            sum1 += __shfl_xor_sync(0xffffffffu, sum1, 2);

            l0 = l0*al0 + sum0;  l1 = l1*al1 + sum1;
            m0r = mn0;  m1r = mn1;

            bool need = (al0 < 1.f) || (al1 < 1.f);
            if (__ballot_sync(0xffffffffu, need)) {
                #pragma unroll
                for (int nt = 0; nt < 16; ++nt) {
                    o[nt][0] *= al0;  o[nt][1] *= al0;
                    o[nt][2] *= al1;  o[nt][3] *= al1;
                }
            }

            if (hn) CPWAIT1(); else CPWAIT0();   // V(j) landed (K(j+1) may fly)
            GBAR(barid);

            // ---- O += P V ----
            #pragma unroll
            for (int t = 0; t < 4; ++t) {
                #pragma unroll
                for (int nbp = 0; nbp < 8; ++nbp) {
                    u32 vh[4], vl[4];
                    u32 ba = vbh + (u32)((nbp*16 + bRow)*VSB + (t*16 + bKB)*2);
                    ldsm4(ba,         vh[0], vh[1], vh[2], vh[3]);
                    ldsm4(ba + 18432, vl[0], vl[1], vl[2], vl[3]);
                    mma16816(o[nbp*2],   ph2[4*t],ph2[4*t+1],ph2[4*t+2],ph2[4*t+3], vh[0], vh[1]);
                    mma16816(o[nbp*2],   ph2[4*t],ph2[4*t+1],ph2[4*t+2],ph2[4*t+3], vl[0], vl[1]);
                    mma16816(o[nbp*2],   pl2[4*t],pl2[4*t+1],pl2[4*t+2],pl2[4*t+3], vh[0], vh[1]);
                    mma16816(o[nbp*2+1], ph2[4*t],ph2[4*t+1],ph2[4*t+2],ph2[4*t+3], vh[2], vh[3]);
                    mma16816(o[nbp*2+1], ph2[4*t],ph2[4*t+1],ph2[4*t+2],ph2[4*t+3], vl[2], vl[3]);
                    mma16816(o[nbp*2+1], pl2[4*t],pl2[4*t+1],pl2[4*t+2],pl2[4*t+3], vh[2], vh[3]);
                }
            }
            GBAR(barid);                 // group done reading V(j)
            if (hn) {
                issueV(j + 1);
                CPWAIT1();               // K(j+1) landed (V(j+1) may fly)
                GBAR(barid);
            }
        }

        // ---- store partials ----
        const int gr0 = brow + rl0, gr1 = brow + rl1;
        #pragma unroll
        for (int nt = 0; nt < 16; ++nt) {
            const int col = nt*8 + (lane & 3)*2;
            *(float2*)&g_Op[(size_t)gr0*DH + col] = make_float2(o[nt][0], o[nt][1]);
            *(float2*)&g_Op[(size_t)gr1*DH + col] = make_float2(o[nt][2], o[nt][3]);
        }
        if ((lane & 3) == 0) {
            g_mrow[gr0] = m0r;  g_lrow[gr0] = l0;
            g_mrow[gr1] = m1r;  g_lrow[gr1] = l1;
        }
        CPWAIT0();          // drain before next unit reuses stages
        GBAR(barid);
    }
}

// =====================================================================
// Kernel 3: merge 4 KV-quarter partials per row (LSE combine), float4.
// grid 2048 x 128 thr: 4 rows/CTA, 32 threads/row, 4 elems/thread.
// =====================================================================
__global__ void merge_kernel(float* __restrict__ Out)
{
    const int t = threadIdx.x;
    const int row = blockIdx.x*4 + (t >> 5);
    const int c = (t & 31)*4;

    float mv[4], lv[4];
    float mmax = NEGINF;
    #pragma unroll
    for (int q = 0; q < 4; ++q) {
        mv[q] = g_mrow[q*SEQ + row];
        lv[q] = g_lrow[q*SEQ + row];
        if (lv[q] > 0.f) mmax = fmaxf(mmax, mv[q]);
    }
    float4 acc = make_float4(0.f, 0.f, 0.f, 0.f);
    float ws = 0.f;
    #pragma unroll
    for (int q = 0; q < 4; ++q) {
        if (lv[q] > 0.f) {
            float wgt = __expf(mv[q] - mmax);
            float4 v = *(const float4*)&g_Op[((size_t)q*SEQ + row)*DH + c];
            acc.x += wgt*v.x; acc.y += wgt*v.y; acc.z += wgt*v.z; acc.w += wgt*v.w;
            ws += wgt * lv[q];
        }
    }
    float inv = 1.0f / ws;
    *(float4*)&Out[(size_t)row*DH + c] =
        make_float4(acc.x*inv, acc.y*inv, acc.z*inv, acc.w*inv);
}

// =====================================================================
extern "C" void kernel_launch(void* const* d_in, const int* in_sizes, int n_in,
                              void* d_out, int out_size)
{
    (void)in_sizes; (void)n_in; (void)out_size;
    const float* X  = (const float*)d_in[0];
    const float* Wq = (const float*)d_in[1];
    const float* Wk = (const float*)d_in[2];
    const float* Wv = (const float*)d_in[3];

    const int nTot = SEQ*DM/4 + 3*DH*DM/4;
    split_all_kernel<<<(nTot + 255)/256, 256>>>(
        (const float4*)X, (const float4*)Wq, (const float4*)Wk, (const float4*)Wv);

    const int PSM = 2*PSSZ;        // 110592
    const int ASM = 2*GSZ;         // 212992
    cudaFuncSetAttribute(proj_kernel, cudaFuncAttributeMaxDynamicSharedMemorySize, PSM);
    cudaFuncSetAttribute(attn_kernel, cudaFuncAttributeMaxDynamicSharedMemorySize, ASM);

    proj_kernel<<<dim3(128, 3), 256, PSM>>>();
    attn_kernel<<<128, 256, ASM>>>();
    merge_kernel<<<SEQ/4, 128>>>((float*)d_out);
}

// round 8
// speedup vs baseline: 1.1808x; 1.1808x over previous
#include <cuda_runtime.h>
#include <cuda_fp16.h>
#include <cstdint>

typedef uint32_t u32;

#define SEQ 8192
#define DM  1024
#define DH  128

#define NEGINF __int_as_float(0xff800000u)

// ---------------- device scratch (no allocs allowed) ----------------
__device__ __align__(16) __half g_Xh[SEQ*DM],  g_Xl[SEQ*DM];
__device__ __align__(16) __half g_Wh[3*DH*DM], g_Wl[3*DH*DM];
__device__ __align__(16) __half g_Qh[SEQ*DH],  g_Ql[SEQ*DH];
__device__ __align__(16) __half g_Kh[SEQ*DH],  g_Kl[SEQ*DH];
__device__ __align__(16) __half g_Vth[DH*SEQ], g_Vtl[DH*SEQ];  // V transposed [dim][seq]
__device__ float g_Op[4*SEQ*DH];
__device__ float g_mrow[4*SEQ], g_lrow[4*SEQ];

// ---------------- helpers ----------------
__device__ __forceinline__ u32 s2u(const void* p){
    u32 a; asm("{ .reg .u64 t; cvta.to.shared.u64 t, %1; cvt.u32.u64 %0, t; }" : "=r"(a) : "l"(p)); return a;
}
// split two floats into fp16 hi + fp16 residual lo (packed f16x2, first float in low half)
__device__ __forceinline__ void split2(float a, float b, u32 &h, u32 &l){
    __half2 hh = __floats2half2_rn(a, b);
    h = *reinterpret_cast<u32*>(&hh);
    float2 bk = __half22float2(hh);
    __half2 ll = __floats2half2_rn(a - bk.x, b - bk.y);
    l = *reinterpret_cast<u32*>(&ll);
}
__device__ __forceinline__ u32 packh2(float a, float b){
    __half2 hh = __floats2half2_rn(a, b);
    return *reinterpret_cast<u32*>(&hh);
}
__device__ __forceinline__ void ldsm4(u32 a, u32 &r0, u32 &r1, u32 &r2, u32 &r3){
    asm volatile("ldmatrix.sync.aligned.m8n8.x4.shared.b16 {%0,%1,%2,%3}, [%4];"
        : "=r"(r0), "=r"(r1), "=r"(r2), "=r"(r3) : "r"(a));
}
__device__ __forceinline__ void mma16816(float* d, u32 a0, u32 a1, u32 a2, u32 a3, u32 b0, u32 b1){
    asm volatile("mma.sync.aligned.m16n8k16.row.col.f32.f16.f16.f32 "
        "{%0,%1,%2,%3},{%4,%5,%6,%7},{%8,%9},{%0,%1,%2,%3};"
        : "+f"(d[0]), "+f"(d[1]), "+f"(d[2]), "+f"(d[3])
        : "r"(a0), "r"(a1), "r"(a2), "r"(a3), "r"(b0), "r"(b1));
}
__device__ __forceinline__ void cpa16(u32 dst, const void* src){
    asm volatile("cp.async.cg.shared.global [%0], [%1], 16;" :: "r"(dst), "l"(src));
}
#define CPCOMMIT() asm volatile("cp.async.commit_group;" ::: "memory")
#define CPWAIT0()  asm volatile("cp.async.wait_group 0;" ::: "memory")

// =====================================================================
// Kernel 0: fp32 -> split fp16 for X and the 3 W matrices
// =====================================================================
__global__ void split_all_kernel(const float4* __restrict__ X,
                                 const float4* __restrict__ Wq,
                                 const float4* __restrict__ Wk,
                                 const float4* __restrict__ Wv)
{
    const int nX4 = SEQ*DM/4, nW4 = DH*DM/4;
    int i = blockIdx.x * blockDim.x + threadIdx.x;
    const float4* src; uint2 *dh, *dl; int off;
    if (i < nX4) {
        src = X; off = i;
        dh = (uint2*)g_Xh; dl = (uint2*)g_Xl;
    } else {
        int k = i - nX4;
        if (k >= 3*nW4) return;
        int mat = k / nW4; off = k - mat*nW4;
        src = (mat==0) ? Wq : (mat==1) ? Wk : Wv;
        dh = (uint2*)(g_Wh + (size_t)mat*DH*DM);
        dl = (uint2*)(g_Wl + (size_t)mat*DH*DM);
    }
    float4 v = src[off];
    u32 h0, l0, h1, l1;
    split2(v.x, v.y, h0, l0);
    split2(v.z, v.w, h1, l1);
    dh[off] = make_uint2(h0, h1);
    dl[off] = make_uint2(l0, l1);
}

// =====================================================================
// Kernel 1: QKV projection, split-fp16 3-term, 2-stream accumulators,
// cp.async 2-stage. grid(128,3): M-tile 64. 256 thr = 8 warps (2m x 4n).
// =====================================================================
#define PSB   144
#define PXH   0
#define PXL   9216
#define PWH   18432
#define PWL   36864
#define PSSZ  55296

__global__ void __launch_bounds__(256,1) proj_kernel()
{
    extern __shared__ __align__(16) char sm[];
    const u32 sb = s2u(sm);

    const int tid = threadIdx.x, lane = tid & 31, wid = tid >> 5;
    const int wm = wid >> 2, wn = wid & 3;       // 2m x 4n
    const int m0 = blockIdx.x * 64, mat = blockIdx.y;
    const __half* __restrict__ Wbh = g_Wh + (size_t)mat*DH*DM;
    const __half* __restrict__ Wbl = g_Wl + (size_t)mat*DH*DM;
    const float scale = (mat==0) ? 0.08838834764831845f : 1.0f;

    const int aRow = lane & 15, aKB = (lane >> 4) << 3;
    const int bRow = (lane & 7) + ((lane >> 4) & 1) * 8, bKB = ((lane >> 3) & 1) << 3;

    auto issue = [&](int kc, int st){
        const u32 base = sb + st*PSSZ;
        #pragma unroll
        for (int it = 0; it < 2; ++it) {
            int idx = tid + it*256;
            int r = idx >> 3, c = idx & 7;
            cpa16(base + PXH + r*PSB + c*16, &g_Xh[(size_t)(m0 + r)*DM + kc*64 + c*8]);
            cpa16(base + PXL + r*PSB + c*16, &g_Xl[(size_t)(m0 + r)*DM + kc*64 + c*8]);
        }
        #pragma unroll
        for (int it = 0; it < 4; ++it) {
            int idx = tid + it*256;
            int r = idx >> 3, c = idx & 7;
            cpa16(base + PWH + r*PSB + c*16, &Wbh[(size_t)r*DM + kc*64 + c*8]);
            cpa16(base + PWL + r*PSB + c*16, &Wbl[(size_t)r*DM + kc*64 + c*8]);
        }
        CPCOMMIT();
    };

    float a1[2][4][4], a2[2][4][4];
    #pragma unroll
    for (int i = 0; i < 2; ++i)
        #pragma unroll
        for (int j = 0; j < 4; ++j)
            #pragma unroll
            for (int c = 0; c < 4; ++c) { a1[i][j][c] = 0.f; a2[i][j][c] = 0.f; }

    issue(0, 0);
    for (int kc = 0; kc < 16; ++kc) {
        const int st = kc & 1;
        const u32 base = sb + st*PSSZ;
        CPWAIT0();
        __syncthreads();
        if (kc + 1 < 16) issue(kc + 1, st ^ 1);

        #pragma unroll
        for (int ks = 0; ks < 4; ++ks) {
            u32 ah[2][4], al[2][4];
            #pragma unroll
            for (int mt = 0; mt < 2; ++mt) {
                u32 qa = base + PXH + (u32)((wm*32 + mt*16 + aRow)*PSB + (ks*16 + aKB)*2);
                ldsm4(qa,             ah[mt][0], ah[mt][1], ah[mt][2], ah[mt][3]);
                ldsm4(qa + (PXL-PXH), al[mt][0], al[mt][1], al[mt][2], al[mt][3]);
            }
            #pragma unroll
            for (int nb = 0; nb < 2; ++nb) {
                u32 bh[4], bl[4];
                u32 ba = base + PWH + (u32)((wn*32 + nb*16 + bRow)*PSB + (ks*16 + bKB)*2);
                ldsm4(ba,             bh[0], bh[1], bh[2], bh[3]);
                ldsm4(ba + (PWL-PWH), bl[0], bl[1], bl[2], bl[3]);
                #pragma unroll
                for (int mt = 0; mt < 2; ++mt) {
                    // stream 1: hi*hi ; stream 2: hi*lo + lo*hi
                    mma16816(a1[mt][nb*2],   ah[mt][0],ah[mt][1],ah[mt][2],ah[mt][3], bh[0], bh[1]);
                    mma16816(a2[mt][nb*2],   ah[mt][0],ah[mt][1],ah[mt][2],ah[mt][3], bl[0], bl[1]);
                    mma16816(a2[mt][nb*2],   al[mt][0],al[mt][1],al[mt][2],al[mt][3], bh[0], bh[1]);
                    mma16816(a1[mt][nb*2+1], ah[mt][0],ah[mt][1],ah[mt][2],ah[mt][3], bh[2], bh[3]);
                    mma16816(a2[mt][nb*2+1], ah[mt][0],ah[mt][1],ah[mt][2],ah[mt][3], bl[2], bl[3]);
                    mma16816(a2[mt][nb*2+1], al[mt][0],al[mt][1],al[mt][2],al[mt][3], bh[2], bh[3]);
                }
            }
        }
        __syncthreads();
    }

    #pragma unroll
    for (int mt = 0; mt < 2; ++mt) {
        const int r0 = m0 + wm*32 + mt*16 + (lane >> 2);
        const int r1 = r0 + 8;
        #pragma unroll
        for (int nt = 0; nt < 4; ++nt) {
            const int col = wn*32 + nt*8 + (lane & 3)*2;
            float c0 = (a1[mt][nt][0] + a2[mt][nt][0])*scale;
            float c1 = (a1[mt][nt][1] + a2[mt][nt][1])*scale;
            float c2 = (a1[mt][nt][2] + a2[mt][nt][2])*scale;
            float c3 = (a1[mt][nt][3] + a2[mt][nt][3])*scale;
            if (mat < 2) {
                __half* GH = (mat==0) ? g_Qh : g_Kh;
                __half* GL = (mat==0) ? g_Ql : g_Kl;
                u32 h, l;
                split2(c0, c1, h, l);
                *(u32*)&GH[(size_t)r0*DH + col] = h;  *(u32*)&GL[(size_t)r0*DH + col] = l;
                split2(c2, c3, h, l);
                *(u32*)&GH[(size_t)r1*DH + col] = h;  *(u32*)&GL[(size_t)r1*DH + col] = l;
            } else {
                float v[4] = {c0, c1, c2, c3};
                #pragma unroll
                for (int e = 0; e < 4; ++e) {
                    int d  = col + (e & 1);
                    int sq = (e < 2) ? r0 : r1;
                    __half h = __float2half_rn(v[e]);
                    g_Vth[(size_t)d*SEQ + sq] = h;
                    g_Vtl[(size_t)d*SEQ + sq] = __float2half_rn(v[e] - __half2float(h));
                }
            }
        }
    }
}

// =====================================================================
// Kernel 2: causal flash attention. fp16: S 3-term (2 streams),
// P single fp16, V split 2-term. cp.async 2-stage K/V.
// 128 CTAs x 256 thr. CTA (qq,pp): KV-quarter qq of q-tiles pp & 63-pp.
// =====================================================================
#define ASB   272                 // Q/K row stride bytes (128 kcols)
#define VSB   144                 // V row stride bytes (64 key cols)
#define AQH   0
#define AQL   34816
#define ASTG  69632               // stage base
#define SKH   0
#define SKL   17408
#define SVH   34816
#define SVL   53248
#define ASSZ  71680               // stage size; total 69632 + 2*71680 = 212992

__global__ void __launch_bounds__(256,1) attn_kernel()
{
    extern __shared__ __align__(16) char sm[];
    const u32 sb = s2u(sm);

    const int tid = threadIdx.x, lane = tid & 31, w = tid >> 5;
    const int qq = blockIdx.x >> 5;   // kv quarter 0..3
    const int pp = blockIdx.x & 31;   // pair id 0..31

    const int aRow = lane & 15, aKB = (lane >> 4) << 3;
    const int bRow = (lane & 7) + ((lane >> 4) & 1) * 8, bKB = ((lane >> 3) & 1) << 3;
    const int rl0 = w*16 + (lane >> 2);
    const int rl1 = rl0 + 8;

    auto issueKV = [&](int j, int st){
        const u32 base = sb + ASTG + st*ASSZ;
        #pragma unroll
        for (int it = 0; it < 4; ++it) {     // K: 64 rows x 16 x16B, hi+lo
            int idx = tid + it*256;
            int r = idx >> 4, c = idx & 15;
            cpa16(base + SKH + r*ASB + c*16, &g_Kh[(size_t)(j*64 + r)*DH + c*8]);
            cpa16(base + SKL + r*ASB + c*16, &g_Kl[(size_t)(j*64 + r)*DH + c*8]);
        }
        #pragma unroll
        for (int it = 0; it < 4; ++it) {     // V: 128 dim-rows x 8 x16B, hi+lo
            int idx = tid + it*256;
            int r = idx >> 3, c = idx & 7;
            cpa16(base + SVH + r*VSB + c*16, &g_Vth[(size_t)r*SEQ + j*64 + c*8]);
            cpa16(base + SVL + r*VSB + c*16, &g_Vtl[(size_t)r*SEQ + j*64 + c*8]);
        }
        CPCOMMIT();
    };

    #pragma unroll 1
    for (int u = 0; u < 2; ++u) {
        const int i  = u ? (63 - pp) : pp;
        const int T2 = 2*(i + 1);              // 64-key subtiles
        const int Tq = (T2 + 3) >> 2;
        const int j0 = qq * Tq;
        const int j1 = (j0 + Tq < T2) ? (j0 + Tq) : T2;
        const int brow = qq*SEQ + i*128;

        if (j0 >= j1) {
            if (tid < 128) { g_mrow[brow + tid] = NEGINF; g_lrow[brow + tid] = 0.f; }
            continue;
        }

        __syncthreads();   // protect Q smem from prior unit's readers
        #pragma unroll
        for (int it = 0; it < 8; ++it) {
            int idx = tid + it*256;
            int r = idx >> 4, c = idx & 15;
            cpa16(sb + AQH + r*ASB + c*16, &g_Qh[(size_t)(i*128 + r)*DH + c*8]);
            cpa16(sb + AQL + r*ASB + c*16, &g_Ql[(size_t)(i*128 + r)*DH + c*8]);
        }
        issueKV(j0, 0);

        float o[16][4];
        #pragma unroll
        for (int nt = 0; nt < 16; ++nt)
            #pragma unroll
            for (int c = 0; c < 4; ++c) o[nt][c] = 0.f;
        float m0r = NEGINF, m1r = NEGINF, l0 = 0.f, l1 = 0.f;

        #pragma unroll 1
        for (int j = j0; j < j1; ++j) {
            const int st = (j - j0) & 1;
            const u32 kb = sb + ASTG + st*ASSZ;
            CPWAIT0();
            __syncthreads();
            if (j + 1 < j1) issueKV(j + 1, st ^ 1);

            // ---- S = Q K^T, 2 accumulation streams ----
            float s1[8][4], s2[8][4];
            #pragma unroll
            for (int nt = 0; nt < 8; ++nt)
                #pragma unroll
                for (int c = 0; c < 4; ++c) { s1[nt][c] = 0.f; s2[nt][c] = 0.f; }

            #pragma unroll
            for (int ks = 0; ks < 8; ++ks) {
                u32 qh[4], ql[4];
                u32 qa = sb + AQH + (u32)((w*16 + aRow)*ASB + (ks*16 + aKB)*2);
                ldsm4(qa,             qh[0], qh[1], qh[2], qh[3]);
                ldsm4(qa + (AQL-AQH), ql[0], ql[1], ql[2], ql[3]);
                #pragma unroll
                for (int nbp = 0; nbp < 4; ++nbp) {
                    u32 kh[4], kl[4];
                    u32 ba = kb + SKH + (u32)((nbp*16 + bRow)*ASB + (ks*16 + bKB)*2);
                    ldsm4(ba,             kh[0], kh[1], kh[2], kh[3]);
                    ldsm4(ba + (SKL-SKH), kl[0], kl[1], kl[2], kl[3]);
                    mma16816(s1[nbp*2],   qh[0],qh[1],qh[2],qh[3], kh[0], kh[1]);
                    mma16816(s2[nbp*2],   qh[0],qh[1],qh[2],qh[3], kl[0], kl[1]);
                    mma16816(s2[nbp*2],   ql[0],ql[1],ql[2],ql[3], kh[0], kh[1]);
                    mma16816(s1[nbp*2+1], qh[0],qh[1],qh[2],qh[3], kh[2], kh[3]);
                    mma16816(s2[nbp*2+1], qh[0],qh[1],qh[2],qh[3], kl[2], kl[3]);
                    mma16816(s2[nbp*2+1], ql[0],ql[1],ql[2],ql[3], kh[2], kh[3]);
                }
            }
            // merge streams
            #pragma unroll
            for (int nt = 0; nt < 8; ++nt)
                #pragma unroll
                for (int c = 0; c < 4; ++c) s1[nt][c] += s2[nt][c];

            // ---- causal mask ----
            if (j*64 + 63 > i*128) {
                const int gr0 = i*128 + rl0, gr1 = i*128 + rl1;
                #pragma unroll
                for (int nt = 0; nt < 8; ++nt) {
                    int gc = j*64 + nt*8 + (lane & 3)*2;
                    if (gc     > gr0) s1[nt][0] = NEGINF;
                    if (gc + 1 > gr0) s1[nt][1] = NEGINF;
                    if (gc     > gr1) s1[nt][2] = NEGINF;
                    if (gc + 1 > gr1) s1[nt][3] = NEGINF;
                }
            }

            // ---- online softmax (quad-local rows) ----
            float mx0 = NEGINF, mx1 = NEGINF;
            #pragma unroll
            for (int nt = 0; nt < 8; ++nt) {
                mx0 = fmaxf(mx0, fmaxf(s1[nt][0], s1[nt][1]));
                mx1 = fmaxf(mx1, fmaxf(s1[nt][2], s1[nt][3]));
            }
            mx0 = fmaxf(mx0, __shfl_xor_sync(0xffffffffu, mx0, 1));
            mx0 = fmaxf(mx0, __shfl_xor_sync(0xffffffffu, mx0, 2));
            mx1 = fmaxf(mx1, __shfl_xor_sync(0xffffffffu, mx1, 1));
            mx1 = fmaxf(mx1, __shfl_xor_sync(0xffffffffu, mx1, 2));

            float mn0 = fmaxf(m0r, mx0), mn1 = fmaxf(m1r, mx1);
            float mue0 = (mn0 == NEGINF) ? 0.f : mn0;
            float mue1 = (mn1 == NEGINF) ? 0.f : mn1;
            float al0 = __expf(m0r - mue0), al1 = __expf(m1r - mue1);

            u32 p2[16];
            float sum0 = 0.f, sum1 = 0.f;
            #pragma unroll
            for (int nt = 0; nt < 8; ++nt) {
                float p0 = __expf(s1[nt][0] - mue0);
                float p1 = __expf(s1[nt][1] - mue0);
                float p2f = __expf(s1[nt][2] - mue1);
                float p3 = __expf(s1[nt][3] - mue1);
                sum0 += p0 + p1;  sum1 += p2f + p3;
                p2[nt*2]   = packh2(p0, p1);
                p2[nt*2+1] = packh2(p2f, p3);
            }
            sum0 += __shfl_xor_sync(0xffffffffu, sum0, 1);
            sum0 += __shfl_xor_sync(0xffffffffu, sum0, 2);
            sum1 += __shfl_xor_sync(0xffffffffu, sum1, 1);
            sum1 += __shfl_xor_sync(0xffffffffu, sum1, 2);

            l0 = l0*al0 + sum0;  l1 = l1*al1 + sum1;
            m0r = mn0;  m1r = mn1;

            bool need = (al0 < 1.f) || (al1 < 1.f);
            if (__ballot_sync(0xffffffffu, need)) {
                #pragma unroll
                for (int nt = 0; nt < 16; ++nt) {
                    o[nt][0] *= al0;  o[nt][1] *= al0;
                    o[nt][2] *= al1;  o[nt][3] *= al1;
                }
            }

            // ---- O += P(fp16) * (Vh + Vl) : 2 MMAs per tile-pair ----
            const u32 vb = sb + ASTG + st*ASSZ;
            #pragma unroll
            for (int t = 0; t < 4; ++t) {
                #pragma unroll
                for (int nbp = 0; nbp < 8; ++nbp) {
                    u32 vh[4], vl[4];
                    u32 ba = vb + SVH + (u32)((nbp*16 + bRow)*VSB + (t*16 + bKB)*2);
                    ldsm4(ba,             vh[0], vh[1], vh[2], vh[3]);
                    ldsm4(ba + (SVL-SVH), vl[0], vl[1], vl[2], vl[3]);
                    mma16816(o[nbp*2],   p2[4*t],p2[4*t+1],p2[4*t+2],p2[4*t+3], vh[0], vh[1]);
                    mma16816(o[nbp*2],   p2[4*t],p2[4*t+1],p2[4*t+2],p2[4*t+3], vl[0], vl[1]);
                    mma16816(o[nbp*2+1], p2[4*t],p2[4*t+1],p2[4*t+2],p2[4*t+3], vh[2], vh[3]);
                    mma16816(o[nbp*2+1], p2[4*t],p2[4*t+1],p2[4*t+2],p2[4*t+3], vl[2], vl[3]);
                }
            }
        }

        // ---- store partials ----
        const int gr0 = brow + rl0, gr1 = brow + rl1;
        #pragma unroll
        for (int nt = 0; nt < 16; ++nt) {
            const int col = nt*8 + (lane & 3)*2;
            *(float2*)&g_Op[(size_t)gr0*DH + col] = make_float2(o[nt][0], o[nt][1]);
            *(float2*)&g_Op[(size_t)gr1*DH + col] = make_float2(o[nt][2], o[nt][3]);
        }
        if ((lane & 3) == 0) {
            g_mrow[gr0] = m0r;  g_lrow[gr0] = l0;
            g_mrow[gr1] = m1r;  g_lrow[gr1] = l1;
        }
        CPWAIT0();
        __syncthreads();
    }
}

// =====================================================================
// Kernel 3: merge 4 KV-quarter partials per row (LSE combine), float4.
// =====================================================================
__global__ void merge_kernel(float* __restrict__ Out)
{
    const int t = threadIdx.x;
    const int row = blockIdx.x*4 + (t >> 5);
    const int c = (t & 31)*4;

    float mv[4], lv[4];
    float mmax = NEGINF;
    #pragma unroll
    for (int q = 0; q < 4; ++q) {
        mv[q] = g_mrow[q*SEQ + row];
        lv[q] = g_lrow[q*SEQ + row];
        if (lv[q] > 0.f) mmax = fmaxf(mmax, mv[q]);
    }
    float4 acc = make_float4(0.f, 0.f, 0.f, 0.f);
    float ws = 0.f;
    #pragma unroll
    for (int q = 0; q < 4; ++q) {
        if (lv[q] > 0.f) {
            float wgt = __expf(mv[q] - mmax);
            float4 v = *(const float4*)&g_Op[((size_t)q*SEQ + row)*DH + c];
            acc.x += wgt*v.x; acc.y += wgt*v.y; acc.z += wgt*v.z; acc.w += wgt*v.w;
            ws += wgt * lv[q];
        }
    }
    float inv = 1.0f / ws;
    *(float4*)&Out[(size_t)row*DH + c] =
        make_float4(acc.x*inv, acc.y*inv, acc.z*inv, acc.w*inv);
}

// =====================================================================
extern "C" void kernel_launch(void* const* d_in, const int* in_sizes, int n_in,
                              void* d_out, int out_size)
{
    (void)in_sizes; (void)n_in; (void)out_size;
    const float* X  = (const float*)d_in[0];
    const float* Wq = (const float*)d_in[1];
    const float* Wk = (const float*)d_in[2];
    const float* Wv = (const float*)d_in[3];

    const int nTot = SEQ*DM/4 + 3*DH*DM/4;
    split_all_kernel<<<(nTot + 255)/256, 256>>>(
        (const float4*)X, (const float4*)Wq, (const float4*)Wk, (const float4*)Wv);

    const int PSM = 2*PSSZ;                 // 110592
    const int ASM = ASTG + 2*ASSZ;          // 212992
    cudaFuncSetAttribute(proj_kernel, cudaFuncAttributeMaxDynamicSharedMemorySize, PSM);
    cudaFuncSetAttribute(attn_kernel, cudaFuncAttributeMaxDynamicSharedMemorySize, ASM);

    proj_kernel<<<dim3(128, 3), 256, PSM>>>();
    attn_kernel<<<128, 256, ASM>>>();
    merge_kernel<<<SEQ/4, 128>>>((float*)d_out);
}

// round 10
// speedup vs baseline: 1.2963x; 1.0978x over previous
#include <cuda_runtime.h>
#include <cuda_fp16.h>
#include <cstdint>

typedef uint32_t u32;

#define SEQ 8192
#define DM  1024
#define DH  128

#define NEGINF __int_as_float(0xff800000u)

// ---------------- device scratch (no allocs allowed) ----------------
__device__ __align__(16) __half g_Xh[SEQ*DM],  g_Xl[SEQ*DM];
__device__ __align__(16) __half g_Wh[3*DH*DM], g_Wl[3*DH*DM];
__device__ __align__(16) __half g_Qh[SEQ*DH],  g_Ql[SEQ*DH];
__device__ __align__(16) __half g_Kh[SEQ*DH],  g_Kl[SEQ*DH];
__device__ __align__(16) __half g_Vt[DH*SEQ];              // V transposed [dim][seq], single fp16
__device__ float g_Op[4*SEQ*DH];
__device__ float g_mrow[4*SEQ], g_lrow[4*SEQ];

// ---------------- helpers ----------------
__device__ __forceinline__ u32 s2u(const void* p){
    u32 a; asm("{ .reg .u64 t; cvta.to.shared.u64 t, %1; cvt.u32.u64 %0, t; }" : "=r"(a) : "l"(p)); return a;
}
// split two floats into fp16 hi + fp16 residual lo (packed f16x2)
__device__ __forceinline__ void split2(float a, float b, u32 &h, u32 &l){
    __half2 hh = __floats2half2_rn(a, b);
    h = *reinterpret_cast<u32*>(&hh);
    float2 bk = __half22float2(hh);
    __half2 ll = __floats2half2_rn(a - bk.x, b - bk.y);
    l = *reinterpret_cast<u32*>(&ll);
}
__device__ __forceinline__ u32 packh2(float a, float b){
    __half2 hh = __floats2half2_rn(a, b);
    return *reinterpret_cast<u32*>(&hh);
}
__device__ __forceinline__ void ldsm4(u32 a, u32 &r0, u32 &r1, u32 &r2, u32 &r3){
    asm volatile("ldmatrix.sync.aligned.m8n8.x4.shared.b16 {%0,%1,%2,%3}, [%4];"
        : "=r"(r0), "=r"(r1), "=r"(r2), "=r"(r3) : "r"(a));
}
__device__ __forceinline__ void mma16816(float* d, u32 a0, u32 a1, u32 a2, u32 a3, u32 b0, u32 b1){
    asm volatile("mma.sync.aligned.m16n8k16.row.col.f32.f16.f16.f32 "
        "{%0,%1,%2,%3},{%4,%5,%6,%7},{%8,%9},{%0,%1,%2,%3};"
        : "+f"(d[0]), "+f"(d[1]), "+f"(d[2]), "+f"(d[3])
        : "r"(a0), "r"(a1), "r"(a2), "r"(a3), "r"(b0), "r"(b1));
}
__device__ __forceinline__ void cpa16(u32 dst, const void* src){
    asm volatile("cp.async.cg.shared.global [%0], [%1], 16;" :: "r"(dst), "l"(src));
}
#define CPCOMMIT() asm volatile("cp.async.commit_group;" ::: "memory")
#define CPWAIT0()  asm volatile("cp.async.wait_group 0;" ::: "memory")

// =====================================================================
// Kernel 0: fp32 -> split fp16 for X and the 3 W matrices
// =====================================================================
__global__ void split_all_kernel(const float4* __restrict__ X,
                                 const float4* __restrict__ Wq,
                                 const float4* __restrict__ Wk,
                                 const float4* __restrict__ Wv)
{
    const int nX4 = SEQ*DM/4, nW4 = DH*DM/4;
    int i = blockIdx.x * blockDim.x + threadIdx.x;
    const float4* src; uint2 *dh, *dl; int off;
    if (i < nX4) {
        src = X; off = i;
        dh = (uint2*)g_Xh; dl = (uint2*)g_Xl;
    } else {
        int k = i - nX4;
        if (k >= 3*nW4) return;
        int mat = k / nW4; off = k - mat*nW4;
        src = (mat==0) ? Wq : (mat==1) ? Wk : Wv;
        dh = (uint2*)(g_Wh + (size_t)mat*DH*DM);
        dl = (uint2*)(g_Wl + (size_t)mat*DH*DM);
    }
    float4 v = src[off];
    u32 h0, l0, h1, l1;
    split2(v.x, v.y, h0, l0);
    split2(v.z, v.w, h1, l1);
    dh[off] = make_uint2(h0, h1);
    dl[off] = make_uint2(l0, l1);
}

// =====================================================================
// Kernel 1: QKV projection, split-fp16 3-term, 2-stream accumulators,
// cp.async 2-stage. grid(128,3): M-tile 64. 256 thr = 8 warps (2m x 4n).
// =====================================================================
#define PSB   144
#define PXH   0
#define PXL   9216
#define PWH   18432
#define PWL   36864
#define PSSZ  55296

__global__ void __launch_bounds__(256,1) proj_kernel()
{
    extern __shared__ __align__(16) char sm[];
    const u32 sb = s2u(sm);

    const int tid = threadIdx.x, lane = tid & 31, wid = tid >> 5;
    const int wm = wid >> 2, wn = wid & 3;       // 2m x 4n
    const int m0 = blockIdx.x * 64, mat = blockIdx.y;
    const __half* __restrict__ Wbh = g_Wh + (size_t)mat*DH*DM;
    const __half* __restrict__ Wbl = g_Wl + (size_t)mat*DH*DM;
    const float scale = (mat==0) ? 0.08838834764831845f : 1.0f;

    const int aRow = lane & 15, aKB = (lane >> 4) << 3;
    const int bRow = (lane & 7) + ((lane >> 4) & 1) * 8, bKB = ((lane >> 3) & 1) << 3;

    auto issue = [&](int kc, int st){
        const u32 base = sb + st*PSSZ;
        #pragma unroll
        for (int it = 0; it < 2; ++it) {
            int idx = tid + it*256;
            int r = idx >> 3, c = idx & 7;
            cpa16(base + PXH + r*PSB + c*16, &g_Xh[(size_t)(m0 + r)*DM + kc*64 + c*8]);
            cpa16(base + PXL + r*PSB + c*16, &g_Xl[(size_t)(m0 + r)*DM + kc*64 + c*8]);
        }
        #pragma unroll
        for (int it = 0; it < 4; ++it) {
            int idx = tid + it*256;
            int r = idx >> 3, c = idx & 7;
            cpa16(base + PWH + r*PSB + c*16, &Wbh[(size_t)r*DM + kc*64 + c*8]);
            cpa16(base + PWL + r*PSB + c*16, &Wbl[(size_t)r*DM + kc*64 + c*8]);
        }
        CPCOMMIT();
    };

    float a1[2][4][4], a2[2][4][4];
    #pragma unroll
    for (int i = 0; i < 2; ++i)
        #pragma unroll
        for (int j = 0; j < 4; ++j)
            #pragma unroll
            for (int c = 0; c < 4; ++c) { a1[i][j][c] = 0.f; a2[i][j][c] = 0.f; }

    issue(0, 0);
    for (int kc = 0; kc < 16; ++kc) {
        const int st = kc & 1;
        const u32 base = sb + st*PSSZ;
        CPWAIT0();
        __syncthreads();
        if (kc + 1 < 16) issue(kc + 1, st ^ 1);

        #pragma unroll
        for (int ks = 0; ks < 4; ++ks) {
            u32 ah[2][4], al[2][4];
            #pragma unroll
            for (int mt = 0; mt < 2; ++mt) {
                u32 qa = base + PXH + (u32)((wm*32 + mt*16 + aRow)*PSB + (ks*16 + aKB)*2);
                ldsm4(qa,             ah[mt][0], ah[mt][1], ah[mt][2], ah[mt][3]);
                ldsm4(qa + (PXL-PXH), al[mt][0], al[mt][1], al[mt][2], al[mt][3]);
            }
            #pragma unroll
            for (int nb = 0; nb < 2; ++nb) {
                u32 bh[4], bl[4];
                u32 ba = base + PWH + (u32)((wn*32 + nb*16 + bRow)*PSB + (ks*16 + bKB)*2);
                ldsm4(ba,             bh[0], bh[1], bh[2], bh[3]);
                ldsm4(ba + (PWL-PWH), bl[0], bl[1], bl[2], bl[3]);
                #pragma unroll
                for (int mt = 0; mt < 2; ++mt) {
                    mma16816(a1[mt][nb*2],   ah[mt][0],ah[mt][1],ah[mt][2],ah[mt][3], bh[0], bh[1]);
                    mma16816(a2[mt][nb*2],   ah[mt][0],ah[mt][1],ah[mt][2],ah[mt][3], bl[0], bl[1]);
                    mma16816(a2[mt][nb*2],   al[mt][0],al[mt][1],al[mt][2],al[mt][3], bh[0], bh[1]);
                    mma16816(a1[mt][nb*2+1], ah[mt][0],ah[mt][1],ah[mt][2],ah[mt][3], bh[2], bh[3]);
                    mma16816(a2[mt][nb*2+1], ah[mt][0],ah[mt][1],ah[mt][2],ah[mt][3], bl[2], bl[3]);
                    mma16816(a2[mt][nb*2+1], al[mt][0],al[mt][1],al[mt][2],al[mt][3], bh[2], bh[3]);
                }
            }
        }
        __syncthreads();
    }

    #pragma unroll
    for (int mt = 0; mt < 2; ++mt) {
        const int r0 = m0 + wm*32 + mt*16 + (lane >> 2);
        const int r1 = r0 + 8;
        #pragma unroll
        for (int nt = 0; nt < 4; ++nt) {
            const int col = wn*32 + nt*8 + (lane & 3)*2;
            float c0 = (a1[mt][nt][0] + a2[mt][nt][0])*scale;
            float c1 = (a1[mt][nt][1] + a2[mt][nt][1])*scale;
            float c2 = (a1[mt][nt][2] + a2[mt][nt][2])*scale;
            float c3 = (a1[mt][nt][3] + a2[mt][nt][3])*scale;
            if (mat < 2) {
                __half* GH = (mat==0) ? g_Qh : g_Kh;
                __half* GL = (mat==0) ? g_Ql : g_Kl;
                u32 h, l;
                split2(c0, c1, h, l);
                *(u32*)&GH[(size_t)r0*DH + col] = h;  *(u32*)&GL[(size_t)r0*DH + col] = l;
                split2(c2, c3, h, l);
                *(u32*)&GH[(size_t)r1*DH + col] = h;  *(u32*)&GL[(size_t)r1*DH + col] = l;
            } else {
                g_Vt[(size_t)(col    )*SEQ + r0] = __float2half_rn(c0);
                g_Vt[(size_t)(col + 1)*SEQ + r0] = __float2half_rn(c1);
                g_Vt[(size_t)(col    )*SEQ + r1] = __float2half_rn(c2);
                g_Vt[(size_t)(col + 1)*SEQ + r1] = __float2half_rn(c3);
            }
        }
    }
}

// =====================================================================
// Kernel 2: causal flash attention. fp16: S 3-term (2 streams),
// P single fp16, V single fp16.
// 256 CTAs x 128 thr (4 warps), 88KB smem -> 2 CTAs/SM: cross-CTA
// warp overlap hides softmax + K/V load bubbles under the partner
// CTA's HMMA stream.
// CTA (qq,pp): KV-quarter qq of 64-row q-tiles pp & 127-pp.
// =====================================================================
#define ASB   272            // Q/K row stride bytes (128 kcols fp16 + pad)
#define VSB   144            // V row stride bytes (64 key cols fp16 + pad)
#define AQH   0
#define AQL   17408
#define AKH   34816
#define AKL   52224
#define AVH   69632
#define ASM_T 88064          // total per CTA

__global__ void __launch_bounds__(128,2) attn_kernel()
{
    extern __shared__ __align__(16) char sm[];
    const u32 sb = s2u(sm);

    const int tid = threadIdx.x, lane = tid & 31, w = tid >> 5;
    const int qq = blockIdx.x >> 6;   // kv quarter 0..3
    const int pp = blockIdx.x & 63;   // pair id 0..63

    const int aRow = lane & 15, aKB = (lane >> 4) << 3;
    const int bRow = (lane & 7) + ((lane >> 4) & 1) * 8, bKB = ((lane >> 3) & 1) << 3;
    const int rl0 = w*16 + (lane >> 2);   // local q-row (0..63)
    const int rl1 = rl0 + 8;

    auto issueKV = [&](int j){
        #pragma unroll
        for (int it = 0; it < 8; ++it) {     // K: 64 rows x 16 chunks, hi+lo (1024 xfers)
            int idx = tid + it*128;
            int r = idx >> 4, c = idx & 15;
            cpa16(sb + AKH + r*ASB + c*16, &g_Kh[(size_t)(j*64 + r)*DH + c*8]);
            cpa16(sb + AKL + r*ASB + c*16, &g_Kl[(size_t)(j*64 + r)*DH + c*8]);
        }
        #pragma unroll
        for (int it = 0; it < 8; ++it) {     // V: 128 dim-rows x 8 chunks (1024 xfers)
            int idx = tid + it*128;
            int r = idx >> 3, c = idx & 7;
            cpa16(sb + AVH + r*VSB + c*16, &g_Vt[(size_t)r*SEQ + j*64 + c*8]);
        }
        CPCOMMIT();
    };

    #pragma unroll 1
    for (int u = 0; u < 2; ++u) {
        const int i  = u ? (127 - pp) : pp;   // 64-row q-tile
        const int Tt = i + 1;                 // 64-key subtiles
        const int Tq = (Tt + 3) >> 2;
        const int j0 = qq * Tq;
        const int j1 = (j0 + Tq < Tt) ? (j0 + Tq) : Tt;
        const int brow = qq*SEQ + i*64;

        if (j0 >= j1) {
            if (tid < 64) { g_mrow[brow + tid] = NEGINF; g_lrow[brow + tid] = 0.f; }
            continue;
        }

        __syncthreads();   // prior unit done reading Q/K/V smem
        // load Q (hi+lo)
        #pragma unroll
        for (int it = 0; it < 8; ++it) {
            int idx = tid + it*128;
            int r = idx >> 4, c = idx & 15;
            cpa16(sb + AQH + r*ASB + c*16, &g_Qh[(size_t)(i*64 + r)*DH + c*8]);
            cpa16(sb + AQL + r*ASB + c*16, &g_Ql[(size_t)(i*64 + r)*DH + c*8]);
        }

        float o[16][4];
        #pragma unroll
        for (int nt = 0; nt < 16; ++nt)
            #pragma unroll
            for (int c = 0; c < 4; ++c) o[nt][c] = 0.f;
        float m0r = NEGINF, m1r = NEGINF, l0 = 0.f, l1 = 0.f;

        #pragma unroll 1
        for (int j = j0; j < j1; ++j) {
            if (j > j0) __syncthreads();   // all warps done reading K/V(j-1)
            issueKV(j);
            CPWAIT0();
            __syncthreads();               // K/V(j) (+Q first time) visible

            // ---- S = Q K^T, 2 accumulation streams ----
            float s1[8][4], s2[8][4];
            #pragma unroll
            for (int nt = 0; nt < 8; ++nt)
                #pragma unroll
                for (int c = 0; c < 4; ++c) { s1[nt][c] = 0.f; s2[nt][c] = 0.f; }

            #pragma unroll
            for (int ks = 0; ks < 8; ++ks) {
                u32 qh[4], ql[4];
                u32 qa = sb + AQH + (u32)((w*16 + aRow)*ASB + (ks*16 + aKB)*2);
                ldsm4(qa,             qh[0], qh[1], qh[2], qh[3]);
                ldsm4(qa + (AQL-AQH), ql[0], ql[1], ql[2], ql[3]);
                #pragma unroll
                for (int nbp = 0; nbp < 4; ++nbp) {
                    u32 kh[4], kl[4];
                    u32 ba = sb + AKH + (u32)((nbp*16 + bRow)*ASB + (ks*16 + bKB)*2);
                    ldsm4(ba,             kh[0], kh[1], kh[2], kh[3]);
                    ldsm4(ba + (AKL-AKH), kl[0], kl[1], kl[2], kl[3]);
                    mma16816(s1[nbp*2],   qh[0],qh[1],qh[2],qh[3], kh[0], kh[1]);
                    mma16816(s2[nbp*2],   qh[0],qh[1],qh[2],qh[3], kl[0], kl[1]);
                    mma16816(s2[nbp*2],   ql[0],ql[1],ql[2],ql[3], kh[0], kh[1]);
                    mma16816(s1[nbp*2+1], qh[0],qh[1],qh[2],qh[3], kh[2], kh[3]);
                    mma16816(s2[nbp*2+1], qh[0],qh[1],qh[2],qh[3], kl[2], kl[3]);
                    mma16816(s2[nbp*2+1], ql[0],ql[1],ql[2],ql[3], kh[2], kh[3]);
                }
            }
            #pragma unroll
            for (int nt = 0; nt < 8; ++nt)
                #pragma unroll
                for (int c = 0; c < 4; ++c) s1[nt][c] += s2[nt][c];

            // ---- causal mask (diagonal subtile only) ----
            if (j == i) {
                const int gr0 = i*64 + rl0, gr1 = i*64 + rl1;
                #pragma unroll
                for (int nt = 0; nt < 8; ++nt) {
                    int gc = j*64 + nt*8 + (lane & 3)*2;
                    if (gc     > gr0) s1[nt][0] = NEGINF;
                    if (gc + 1 > gr0) s1[nt][1] = NEGINF;
                    if (gc     > gr1) s1[nt][2] = NEGINF;
                    if (gc + 1 > gr1) s1[nt][3] = NEGINF;
                }
            }

            // ---- online softmax (quad-local rows) ----
            float mx0 = NEGINF, mx1 = NEGINF;
            #pragma unroll
            for (int nt = 0; nt < 8; ++nt) {
                mx0 = fmaxf(mx0, fmaxf(s1[nt][0], s1[nt][1]));
                mx1 = fmaxf(mx1, fmaxf(s1[nt][2], s1[nt][3]));
            }
            mx0 = fmaxf(mx0, __shfl_xor_sync(0xffffffffu, mx0, 1));
            mx0 = fmaxf(mx0, __shfl_xor_sync(0xffffffffu, mx0, 2));
            mx1 = fmaxf(mx1, __shfl_xor_sync(0xffffffffu, mx1, 1));
            mx1 = fmaxf(mx1, __shfl_xor_sync(0xffffffffu, mx1, 2));

            float mn0 = fmaxf(m0r, mx0), mn1 = fmaxf(m1r, mx1);
            float al0 = __expf(m0r - mn0), al1 = __expf(m1r - mn1);

            u32 p2[16];
            float sum0 = 0.f, sum1 = 0.f;
            #pragma unroll
            for (int nt = 0; nt < 8; ++nt) {
                float p0  = __expf(s1[nt][0] - mn0);
                float p1  = __expf(s1[nt][1] - mn0);
                float p2f = __expf(s1[nt][2] - mn1);
                float p3  = __expf(s1[nt][3] - mn1);
                sum0 += p0 + p1;  sum1 += p2f + p3;
                p2[nt*2]   = packh2(p0, p1);
                p2[nt*2+1] = packh2(p2f, p3);
            }
            sum0 += __shfl_xor_sync(0xffffffffu, sum0, 1);
            sum0 += __shfl_xor_sync(0xffffffffu, sum0, 2);
            sum1 += __shfl_xor_sync(0xffffffffu, sum1, 1);
            sum1 += __shfl_xor_sync(0xffffffffu, sum1, 2);

            l0 = l0*al0 + sum0;  l1 = l1*al1 + sum1;
            m0r = mn0;  m1r = mn1;

            bool need = (al0 < 1.f) || (al1 < 1.f);
            if (__ballot_sync(0xffffffffu, need)) {
                #pragma unroll
                for (int nt = 0; nt < 16; ++nt) {
                    o[nt][0] *= al0;  o[nt][1] *= al0;
                    o[nt][2] *= al1;  o[nt][3] *= al1;
                }
            }

            // ---- O += P(fp16) * V(fp16) ----
            #pragma unroll
            for (int t = 0; t < 4; ++t) {
                #pragma unroll
                for (int nbp = 0; nbp < 8; ++nbp) {
                    u32 vh[4];
                    u32 ba = sb + AVH + (u32)((nbp*16 + bRow)*VSB + (t*16 + bKB)*2);
                    ldsm4(ba, vh[0], vh[1], vh[2], vh[3]);
                    mma16816(o[nbp*2],   p2[4*t],p2[4*t+1],p2[4*t+2],p2[4*t+3], vh[0], vh[1]);
                    mma16816(o[nbp*2+1], p2[4*t],p2[4*t+1],p2[4*t+2],p2[4*t+3], vh[2], vh[3]);
                }
            }
        }

        // ---- store partials ----
        const int gr0 = brow + rl0, gr1 = brow + rl1;
        #pragma unroll
        for (int nt = 0; nt < 16; ++nt) {
            const int col = nt*8 + (lane & 3)*2;
            *(float2*)&g_Op[(size_t)gr0*DH + col] = make_float2(o[nt][0], o[nt][1]);
            *(float2*)&g_Op[(size_t)gr1*DH + col] = make_float2(o[nt][2], o[nt][3]);
        }
        if ((lane & 3) == 0) {
            g_mrow[gr0] = m0r;  g_lrow[gr0] = l0;
            g_mrow[gr1] = m1r;  g_lrow[gr1] = l1;
        }
    }
}

// =====================================================================
// Kernel 3: merge 4 KV-quarter partials per row (LSE combine), float4.
// =====================================================================
__global__ void merge_kernel(float* __restrict__ Out)
{
    const int t = threadIdx.x;
    const int row = blockIdx.x*4 + (t >> 5);
    const int c = (t & 31)*4;

    float mv[4], lv[4];
    float mmax = NEGINF;
    #pragma unroll
    for (int q = 0; q < 4; ++q) {
        mv[q] = g_mrow[q*SEQ + row];
        lv[q] = g_lrow[q*SEQ + row];
        if (lv[q] > 0.f) mmax = fmaxf(mmax, mv[q]);
    }
    float4 acc = make_float4(0.f, 0.f, 0.f, 0.f);
    float ws = 0.f;
    #pragma unroll
    for (int q = 0; q < 4; ++q) {
        if (lv[q] > 0.f) {
            float wgt = __expf(mv[q] - mmax);
            float4 v = *(const float4*)&g_Op[((size_t)q*SEQ + row)*DH + c];
            acc.x += wgt*v.x; acc.y += wgt*v.y; acc.z += wgt*v.z; acc.w += wgt*v.w;
            ws += wgt * lv[q];
        }
    }
    float inv = 1.0f / ws;
    *(float4*)&Out[(size_t)row*DH + c] =
        make_float4(acc.x*inv, acc.y*inv, acc.z*inv, acc.w*inv);
}

// =====================================================================
extern "C" void kernel_launch(void* const* d_in, const int* in_sizes, int n_in,
                              void* d_out, int out_size)
{
    (void)in_sizes; (void)n_in; (void)out_size;
    const float* X  = (const float*)d_in[0];
    const float* Wq = (const float*)d_in[1];
    const float* Wk = (const float*)d_in[2];
    const float* Wv = (const float*)d_in[3];

    const int nTot = SEQ*DM/4 + 3*DH*DM/4;
    split_all_kernel<<<(nTot + 255)/256, 256>>>(
        (const float4*)X, (const float4*)Wq, (const float4*)Wk, (const float4*)Wv);

    const int PSM = 2*PSSZ;                 // 110592
    cudaFuncSetAttribute(proj_kernel, cudaFuncAttributeMaxDynamicSharedMemorySize, PSM);
    cudaFuncSetAttribute(attn_kernel, cudaFuncAttributeMaxDynamicSharedMemorySize, ASM_T);

    proj_kernel<<<dim3(128, 3), 256, PSM>>>();
    attn_kernel<<<256, 128, ASM_T>>>();
    merge_kernel<<<SEQ/4, 128>>>((float*)d_out);
}